// round 3
// baseline (speedup 1.0000x reference)
#include <cuda_runtime.h>
#include <math.h>

#define NINST 65536
#define RNN   512
#define G4    2048
#define SMAX  48
#define MROWS 65472
#define NOUT  961
#define S1 ((size_t)MROWS * 320)

// ---------------- static scratch (allocation-free) ----------------
__device__ float g_xg[(size_t)NINST * G4];   // 512 MB: input-side gate preacts
__device__ float g_h [(size_t)NINST * RNN];  // 128 MB: h history (unmasked)
__device__ float g_c [(size_t)NINST * RNN];  // 128 MB: c history (unmasked)
__device__ int   g_cnt[SMAX];
__device__ int   g_list[(size_t)SMAX * NINST];

typedef unsigned long long u64;

__device__ __forceinline__ u64 pk2(float a){
    u64 r; unsigned u = __float_as_uint(a);
    asm("mov.b64 %0,{%1,%1};" : "=l"(r) : "r"(u));
    return r;
}
__device__ __forceinline__ void fma2(u64& d, u64 a, u64 b){
    asm("fma.rn.f32x2 %0,%1,%2,%0;" : "+l"(d) : "l"(a), "l"(b));
}
__device__ __forceinline__ float2 up2(u64 v){
    unsigned lo, hi;
    asm("mov.b64 {%0,%1},%2;" : "=r"(lo), "=r"(hi) : "l"(v));
    return make_float2(__uint_as_float(lo), __uint_as_float(hi));
}
__device__ __forceinline__ float sigf(float x){ return 1.0f/(1.0f + __expf(-x)); }

// ---------------- reset per-run state ----------------
__global__ void k_zero(){
    if (threadIdx.x < SMAX) g_cnt[threadIdx.x] = 0;
}

// ---------------- segmentation: bucket instances by local step ----------------
__global__ void k_seg(const int* __restrict__ dones){
    int m = blockIdx.x*256 + threadIdx.x;
    if (m >= NINST) return;
    int b = m >> 10, t = m & 1023;
    const int* db = dones + b*1024;
    int s = 0;
    for (int tt = t-1; tt >= 0; --tt){
        if (db[tt]) break;
        if (++s >= SMAX) break;
    }
    if (s < SMAX){
        int p = atomicAdd(&g_cnt[s], 1);
        g_list[s*NINST + p] = m;
    }
}

// ---------------- phase A: x_gates = concat(z, emb[a]) @ W_ih^T + b_ih + b_hh --
__global__ void __launch_bounds__(256) k_phaseA(
    const float* __restrict__ z, const int* __restrict__ act,
    const float* __restrict__ emb, const float* __restrict__ Wih,
    const float* __restrict__ bih, const float* __restrict__ bhh)
{
    __shared__ float As[64][69];
    __shared__ float Ws[68][66];
    __shared__ float bs[64];
    const int tid = threadIdx.x;
    const int rt = blockIdx.x >> 5, ct = blockIdx.x & 31;
    const int m0 = rt*64, g0 = ct*64;

    for (int idx = tid; idx < 64*68; idx += 256){
        int c = idx / 68, f = idx - c*68;
        Ws[f][c] = Wih[(g0 + c)*68 + f];
    }
    if (tid < 64) bs[tid] = bih[g0+tid] + bhh[g0+tid];
    for (int idx = tid; idx < 64*68; idx += 256){
        int r = idx / 68, f = idx - r*68;
        int m = m0 + r;
        As[r][f] = (f < 64) ? z[(size_t)m*64 + f] : emb[act[m]*4 + (f-64)];
    }
    __syncthreads();

    const int ti = tid >> 4, tc = tid & 15;
    u64 acc[4][2];
    #pragma unroll
    for (int r=0;r<4;r++){ acc[r][0]=0; acc[r][1]=0; }

    for (int f = 0; f < 68; ++f){
        u64 w0 = *(const u64*)&Ws[f][4*tc];
        u64 w1 = *(const u64*)&Ws[f][4*tc+2];
        #pragma unroll
        for (int r=0;r<4;r++){
            u64 a = pk2(As[ti*4+r][f]);
            fma2(acc[r][0], a, w0);
            fma2(acc[r][1], a, w1);
        }
    }
    #pragma unroll
    for (int r=0;r<4;r++){
        int m = m0 + ti*4 + r;
        float2 p0 = up2(acc[r][0]), p1 = up2(acc[r][1]);
        float4 v = make_float4(p0.x + bs[4*tc], p0.y + bs[4*tc+1],
                               p1.x + bs[4*tc+2], p1.y + bs[4*tc+3]);
        *(float4*)&g_xg[(size_t)m*G4 + g0 + 4*tc] = v;
    }
}

// ---------------- recurrence for local step s: gates = xg + h_prev @ W_hh^T, cell
// Block tile: 64 instances x 128 packed gate cols = 32 hidden cols x 4 quadrants,
// so the LSTM cell is applied in the epilogue without touching DRAM for gates.
__global__ void __launch_bounds__(256) k_rec(const float* __restrict__ Whh, int s){
    __shared__ union {
        struct { float A[16][68]; float W[16][130]; } g;
        float gate[64][129];
    } sm;
    __shared__ int ml[64];
    const int cnt = g_cnt[s];
    if (cnt == 0) return;
    const int n_rt = (cnt + 63) >> 6;
    const int n_items = n_rt << 4;          // 16 col tiles (2048 / 4 / 32)
    const int tid = threadIdx.x;
    const int ti = tid >> 4, tc = tid & 15;
    const int rr = tid >> 2, kb = 4 * (tid & 3);

    for (int item = blockIdx.x; item < n_items; item += gridDim.x){
        const int rt = item >> 4, ct = item & 15;
        __syncthreads();                     // protect ml/gate reuse from prev iter
        if (tid < 64){
            int i = rt*64 + tid;
            ml[tid] = (i < cnt) ? g_list[s*NINST + i] : -1;
        }
        __syncthreads();

        u64 acc[4][4];
        #pragma unroll
        for (int r=0;r<4;r++){ acc[r][0]=0; acc[r][1]=0; acc[r][2]=0; acc[r][3]=0; }

        if (s > 0){
            int mrow = ml[rr]; if (mrow < 0) mrow = ml[0];
            const float* aP = g_h + (size_t)(mrow-1)*RNN + kb;
            const int c0 = rr, c1 = rr + 64;
            const int q0 = c0 >> 5, q1 = c1 >> 5;
            const float* wP0 = Whh + (size_t)(q0*512 + ct*32 + (c0 & 31))*RNN + kb;
            const float* wP1 = Whh + (size_t)(q1*512 + ct*32 + (c1 & 31))*RNN + kb;

            for (int kk = 0; kk < RNN; kk += 16){
                float4 av = *(const float4*)(aP + kk);
                float4 w0 = *(const float4*)(wP0 + kk);
                float4 w1 = *(const float4*)(wP1 + kk);
                sm.g.A[kb+0][rr]=av.x; sm.g.A[kb+1][rr]=av.y;
                sm.g.A[kb+2][rr]=av.z; sm.g.A[kb+3][rr]=av.w;
                sm.g.W[kb+0][c0]=w0.x; sm.g.W[kb+1][c0]=w0.y;
                sm.g.W[kb+2][c0]=w0.z; sm.g.W[kb+3][c0]=w0.w;
                sm.g.W[kb+0][c1]=w1.x; sm.g.W[kb+1][c1]=w1.y;
                sm.g.W[kb+2][c1]=w1.z; sm.g.W[kb+3][c1]=w1.w;
                __syncthreads();
                #pragma unroll
                for (int k=0;k<16;k++){
                    float4 a4 = *(const float4*)&sm.g.A[k][ti*4];
                    u64 b0 = *(const u64*)&sm.g.W[k][8*tc];
                    u64 b1 = *(const u64*)&sm.g.W[k][8*tc+2];
                    u64 b2 = *(const u64*)&sm.g.W[k][8*tc+4];
                    u64 b3 = *(const u64*)&sm.g.W[k][8*tc+6];
                    u64 a0=pk2(a4.x), a1=pk2(a4.y), a2=pk2(a4.z), a3=pk2(a4.w);
                    fma2(acc[0][0],a0,b0); fma2(acc[0][1],a0,b1); fma2(acc[0][2],a0,b2); fma2(acc[0][3],a0,b3);
                    fma2(acc[1][0],a1,b0); fma2(acc[1][1],a1,b1); fma2(acc[1][2],a1,b2); fma2(acc[1][3],a1,b3);
                    fma2(acc[2][0],a2,b0); fma2(acc[2][1],a2,b1); fma2(acc[2][2],a2,b2); fma2(acc[2][3],a2,b3);
                    fma2(acc[3][0],a3,b0); fma2(acc[3][1],a3,b1); fma2(acc[3][2],a3,b2); fma2(acc[3][3],a3,b3);
                }
                __syncthreads();
            }
        }

        // spill gate tile to smem so i/f/g/o meet per hidden column
        #pragma unroll
        for (int r=0;r<4;r++){
            #pragma unroll
            for (int p=0;p<4;p++){
                float2 v = up2(acc[r][p]);
                sm.gate[ti*4+r][8*tc + 2*p]     = v.x;
                sm.gate[ti*4+r][8*tc + 2*p + 1] = v.y;
            }
        }
        __syncthreads();

        // LSTM cell: 8 cells per thread (64 rows x 32 hidden cols)
        {
            int m = ml[rr];
            if (m >= 0){
                #pragma unroll
                for (int j=0;j<8;j++){
                    int hc = 8*(tid&3) + j;
                    int hcol = ct*32 + hc;
                    const float* xg = g_xg + (size_t)m*G4 + hcol;
                    float xi = sm.gate[rr][hc]       + xg[0];
                    float xf = sm.gate[rr][32 + hc]  + xg[512];
                    float xgg= sm.gate[rr][64 + hc]  + xg[1024];
                    float xo = sm.gate[rr][96 + hc]  + xg[1536];
                    float cp = (s > 0) ? g_c[(size_t)(m-1)*RNN + hcol] : 0.0f;
                    float cn = sigf(xf)*cp + sigf(xi)*tanhf(xgg);
                    float hn = sigf(xo)*tanhf(cn);
                    g_h[(size_t)m*RNN + hcol] = hn;
                    g_c[(size_t)m*RNN + hcol] = cn;
                }
            }
        }
    }
}

// ---------------- phase C: out = h @ W_out^T + b_out, scattered to final layout --
__global__ void __launch_bounds__(256) k_phaseC(
    const float* __restrict__ Wout, const float* __restrict__ bout,
    float* __restrict__ out)
{
    __shared__ float As[16][68];
    __shared__ float Ws[16][130];
    __shared__ int msrc[64];
    const int tid = threadIdx.x;
    const int rt = blockIdx.x >> 3, ct = blockIdx.x & 7;
    const int mo0 = rt*64, n0 = ct*128;
    const int ti = tid >> 4, tc = tid & 15;
    const int rr = tid >> 2, kb = 4 * (tid & 3);

    if (tid < 64){
        int mo = mo0 + tid;
        int b = mo / 1023;
        msrc[tid] = b*1024 + (mo - b*1023);
    }
    __syncthreads();

    u64 acc[4][4];
    #pragma unroll
    for (int r=0;r<4;r++){ acc[r][0]=0; acc[r][1]=0; acc[r][2]=0; acc[r][3]=0; }

    const float* aP = g_h + (size_t)msrc[rr]*RNN + kb;
    const int nc0 = n0 + rr, nc1 = n0 + rr + 64;
    const bool v0 = (nc0 < NOUT), v1 = (nc1 < NOUT);
    const float* wP0 = Wout + (size_t)(v0 ? nc0 : 0)*RNN + kb;
    const float* wP1 = Wout + (size_t)(v1 ? nc1 : 0)*RNN + kb;

    for (int kk = 0; kk < RNN; kk += 16){
        float4 av = *(const float4*)(aP + kk);
        float4 w0 = v0 ? *(const float4*)(wP0 + kk) : make_float4(0,0,0,0);
        float4 w1 = v1 ? *(const float4*)(wP1 + kk) : make_float4(0,0,0,0);
        As[kb+0][rr]=av.x; As[kb+1][rr]=av.y; As[kb+2][rr]=av.z; As[kb+3][rr]=av.w;
        Ws[kb+0][rr]=w0.x; Ws[kb+1][rr]=w0.y; Ws[kb+2][rr]=w0.z; Ws[kb+3][rr]=w0.w;
        Ws[kb+0][rr+64]=w1.x; Ws[kb+1][rr+64]=w1.y; Ws[kb+2][rr+64]=w1.z; Ws[kb+3][rr+64]=w1.w;
        __syncthreads();
        #pragma unroll
        for (int k=0;k<16;k++){
            float4 a4 = *(const float4*)&As[k][ti*4];
            u64 b0 = *(const u64*)&Ws[k][8*tc];
            u64 b1 = *(const u64*)&Ws[k][8*tc+2];
            u64 b2 = *(const u64*)&Ws[k][8*tc+4];
            u64 b3 = *(const u64*)&Ws[k][8*tc+6];
            u64 a0=pk2(a4.x), a1=pk2(a4.y), a2=pk2(a4.z), a3=pk2(a4.w);
            fma2(acc[0][0],a0,b0); fma2(acc[0][1],a0,b1); fma2(acc[0][2],a0,b2); fma2(acc[0][3],a0,b3);
            fma2(acc[1][0],a1,b0); fma2(acc[1][1],a1,b1); fma2(acc[1][2],a1,b2); fma2(acc[1][3],a1,b3);
            fma2(acc[2][0],a2,b0); fma2(acc[2][1],a2,b1); fma2(acc[2][2],a2,b2); fma2(acc[2][3],a2,b3);
            fma2(acc[3][0],a3,b0); fma2(acc[3][1],a3,b1); fma2(acc[3][2],a3,b2); fma2(acc[3][3],a3,b3);
        }
        __syncthreads();
    }

    #pragma unroll
    for (int r=0;r<4;r++){
        int mo = mo0 + ti*4 + r;
        float v[8];
        #pragma unroll
        for (int p=0;p<4;p++){
            float2 x = up2(acc[r][p]);
            v[2*p] = x.x; v[2*p+1] = x.y;
        }
        #pragma unroll
        for (int j=0;j<8;j++){
            int n = n0 + 8*tc + j;
            if (n < NOUT){
                float val = v[j] + bout[n];
                size_t dst;
                if (n < 320)        dst = (size_t)mo*320 + n;
                else if (n < 640)   dst = S1   + (size_t)mo*320 + (n-320);
                else if (n < 960)   dst = 2*S1 + (size_t)mo*320 + (n-640);
                else                dst = 3*S1 + (size_t)mo;
                out[dst] = val;
            }
        }
    }
}

// ---------------- in-place log-softmax over mixture groups of 5 ----------------
__global__ void k_lsm(float* __restrict__ out){
    size_t g = (size_t)blockIdx.x*256 + threadIdx.x;
    if (g >= (size_t)MROWS*64) return;
    float* p = out + g*5;
    float a0=p[0], a1=p[1], a2=p[2], a3=p[3], a4=p[4];
    float mx = fmaxf(fmaxf(fmaxf(a0,a1), fmaxf(a2,a3)), a4);
    float sum = expf(a0-mx)+expf(a1-mx)+expf(a2-mx)+expf(a3-mx)+expf(a4-mx);
    float l = mx + logf(sum);
    p[0]=a0-l; p[1]=a1-l; p[2]=a2-l; p[3]=a3-l; p[4]=a4-l;
}

// ---------------- launch ----------------
extern "C" void kernel_launch(void* const* d_in, const int* in_sizes, int n_in,
                              void* d_out, int out_size) {
    const float* z    = (const float*)d_in[0];
    const int*   act  = (const int*)  d_in[1];
    const int*   don  = (const int*)  d_in[2];
    const float* emb  = (const float*)d_in[3];
    const float* Wih  = (const float*)d_in[4];
    const float* Whh  = (const float*)d_in[5];
    const float* bih  = (const float*)d_in[6];
    const float* bhh  = (const float*)d_in[7];
    const float* Wout = (const float*)d_in[8];
    const float* bout = (const float*)d_in[9];
    float* out = (float*)d_out;

    k_zero<<<1, 64>>>();
    k_seg<<<NINST/256, 256>>>(don);
    k_phaseA<<<(NINST/64)*(G4/64), 256>>>(z, act, emb, Wih, bih, bhh);
    for (int s = 0; s < SMAX; ++s)
        k_rec<<<1184, 256>>>(Whh, s);
    k_phaseC<<<(MROWS/64)*8, 256>>>(Wout, bout, out);
    k_lsm<<<(int)(((size_t)MROWS*64 + 255)/256), 256>>>(out);
}

// round 6
// speedup vs baseline: 1.6840x; 1.6840x over previous
#include <cuda_runtime.h>
#include <math.h>

#define NINST 65536
#define RNN   512
#define G4    2048
#define SMAX  48
#define MROWS 65472
#define NOUT  961
#define S1 ((size_t)MROWS * 320)

// ---------------- static scratch (allocation-free) ----------------
__device__ float g_xg[(size_t)NINST * G4];   // 512 MB: input-side gate preacts
__device__ float g_h [(size_t)NINST * RNN];  // 128 MB: h history
__device__ float g_c [(size_t)NINST * RNN];  // 128 MB: c history
__device__ int   g_cnt[SMAX];
__device__ int   g_list[(size_t)SMAX * NINST];

typedef unsigned long long u64;

__device__ __forceinline__ u64 pk2(float a){
    u64 r; unsigned u = __float_as_uint(a);
    asm("mov.b64 %0,{%1,%1};" : "=l"(r) : "r"(u));
    return r;
}
__device__ __forceinline__ void fma2(u64& d, u64 a, u64 b){
    asm("fma.rn.f32x2 %0,%1,%2,%0;" : "+l"(d) : "l"(a), "l"(b));
}
__device__ __forceinline__ float2 up2(u64 v){
    unsigned lo, hi;
    asm("mov.b64 {%0,%1},%2;" : "=r"(lo), "=r"(hi) : "l"(v));
    return make_float2(__uint_as_float(lo), __uint_as_float(hi));
}
__device__ __forceinline__ float sigf(float x){ return 1.0f/(1.0f + __expf(-x)); }

// ---------------- reset per-run state ----------------
__global__ void k_zero(){
    if (threadIdx.x < SMAX) g_cnt[threadIdx.x] = 0;
}

// ---------------- segmentation: bucket instances by local step ----------------
__global__ void k_seg(const int* __restrict__ dones){
    int m = blockIdx.x*256 + threadIdx.x;
    if (m >= NINST) return;
    int b = m >> 10, t = m & 1023;
    const int* db = dones + b*1024;
    int s = 0;
    for (int tt = t-1; tt >= 0; --tt){
        if (db[tt]) break;
        if (++s >= SMAX) break;
    }
    if (s < SMAX){
        int p = atomicAdd(&g_cnt[s], 1);
        g_list[s*NINST + p] = m;
    }
}

// ---------------- phase A: x_gates = concat(z, emb[a]) @ W_ih^T + b_ih + b_hh --
__global__ void __launch_bounds__(256) k_phaseA(
    const float* __restrict__ z, const int* __restrict__ act,
    const float* __restrict__ emb, const float* __restrict__ Wih,
    const float* __restrict__ bih, const float* __restrict__ bhh)
{
    __shared__ __align__(16) float As[64][69];
    __shared__ __align__(16) float Ws[68][66];
    __shared__ float bs[64];
    const int tid = threadIdx.x;
    const int rt = blockIdx.x >> 5, ct = blockIdx.x & 31;
    const int m0 = rt*64, g0 = ct*64;

    for (int idx = tid; idx < 64*68; idx += 256){
        int c = idx / 68, f = idx - c*68;
        Ws[f][c] = Wih[(g0 + c)*68 + f];
    }
    if (tid < 64) bs[tid] = bih[g0+tid] + bhh[g0+tid];
    for (int idx = tid; idx < 64*68; idx += 256){
        int r = idx / 68, f = idx - r*68;
        int m = m0 + r;
        As[r][f] = (f < 64) ? z[(size_t)m*64 + f] : emb[act[m]*4 + (f-64)];
    }
    __syncthreads();

    const int ti = tid >> 4, tc = tid & 15;
    u64 acc[4][2];
    #pragma unroll
    for (int r=0;r<4;r++){ acc[r][0]=0; acc[r][1]=0; }

    for (int f = 0; f < 68; ++f){
        u64 w0 = *(const u64*)&Ws[f][4*tc];
        u64 w1 = *(const u64*)&Ws[f][4*tc+2];
        #pragma unroll
        for (int r=0;r<4;r++){
            u64 a = pk2(As[ti*4+r][f]);
            fma2(acc[r][0], a, w0);
            fma2(acc[r][1], a, w1);
        }
    }
    #pragma unroll
    for (int r=0;r<4;r++){
        int m = m0 + ti*4 + r;
        float2 p0 = up2(acc[r][0]), p1 = up2(acc[r][1]);
        float4 v = make_float4(p0.x + bs[4*tc], p0.y + bs[4*tc+1],
                               p1.x + bs[4*tc+2], p1.y + bs[4*tc+3]);
        *(float4*)&g_xg[(size_t)m*G4 + g0 + 4*tc] = v;
    }
}

// ---------------- recurrence v2: 128x128 tiles, double-buffered, fused cell ----
// Tile: 128 instances x 128 gate cols; smem col c -> quadrant q=c>>5 (i,f,g,o),
// hidden col = ct*32 + (c&31). Thread (ti,tc) owns rows ti*8..+7 and cols
// {2tc+32p}, p=0..3 => all 4 gates of hidden pair (2tc,2tc+1): cell is local.
__global__ void __launch_bounds__(256, 2) k_rec(const float* __restrict__ Whh, int s){
    __shared__ __align__(16) float As[2][16][132];
    __shared__ __align__(16) float Ws[2][16][132];
    __shared__ int ml[128];
    const int cnt = g_cnt[s];
    if (cnt == 0) return;
    const int n_rt = (cnt + 127) >> 7;
    const int n_items = n_rt << 4;
    const int tid = threadIdx.x;
    const int ti = tid >> 4, tc = tid & 15;
    const int ar0 = tid & 127, sg0 = tid >> 7;   // staging: row/col id, base seg

    for (int item = blockIdx.x; item < n_items; item += gridDim.x){
        const int rt = item >> 4, ct = item & 15;
        __syncthreads();
        if (tid < 128){
            int i = rt*128 + tid;
            ml[tid] = (i < cnt) ? g_list[s*NINST + i] : -1;
        }
        __syncthreads();

        u64 acc[8][4];
        #pragma unroll
        for (int r=0;r<8;r++){
            #pragma unroll
            for (int p=0;p<4;p++) acc[r][p] = 0;
        }

        if (s > 0){
            const float* wbase = Whh + (size_t)((ar0>>5)*512 + ct*32 + (ar0&31))*RNN;
            int am = ml[ar0]; if (am < 0) am = ml[0];
            const float* abase = g_h + (size_t)(am-1)*RNN;

            float4 aV[2], wV[2];
            #pragma unroll
            for (int i=0;i<2;i++){
                aV[i] = *(const float4*)(abase + (sg0+2*i)*4);
                wV[i] = *(const float4*)(wbase + (sg0+2*i)*4);
            }
            int p = 0;
            for (int kk = 0; kk < RNN; kk += 16){
                #pragma unroll
                for (int i=0;i<2;i++){
                    int seg = sg0 + 2*i;
                    As[p][seg*4+0][ar0]=aV[i].x; As[p][seg*4+1][ar0]=aV[i].y;
                    As[p][seg*4+2][ar0]=aV[i].z; As[p][seg*4+3][ar0]=aV[i].w;
                    Ws[p][seg*4+0][ar0]=wV[i].x; Ws[p][seg*4+1][ar0]=wV[i].y;
                    Ws[p][seg*4+2][ar0]=wV[i].z; Ws[p][seg*4+3][ar0]=wV[i].w;
                }
                __syncthreads();
                if (kk + 16 < RNN){
                    #pragma unroll
                    for (int i=0;i<2;i++){
                        aV[i] = *(const float4*)(abase + kk+16 + (sg0+2*i)*4);
                        wV[i] = *(const float4*)(wbase + kk+16 + (sg0+2*i)*4);
                    }
                }
                #pragma unroll
                for (int k=0;k<16;k++){
                    float4 a0 = *(const float4*)&As[p][k][ti*8];
                    float4 a1 = *(const float4*)&As[p][k][ti*8+4];
                    u64 b0 = *(const u64*)&Ws[p][k][2*tc];
                    u64 b1 = *(const u64*)&Ws[p][k][2*tc+32];
                    u64 b2 = *(const u64*)&Ws[p][k][2*tc+64];
                    u64 b3 = *(const u64*)&Ws[p][k][2*tc+96];
                    u64 pa;
                    pa=pk2(a0.x); fma2(acc[0][0],pa,b0); fma2(acc[0][1],pa,b1); fma2(acc[0][2],pa,b2); fma2(acc[0][3],pa,b3);
                    pa=pk2(a0.y); fma2(acc[1][0],pa,b0); fma2(acc[1][1],pa,b1); fma2(acc[1][2],pa,b2); fma2(acc[1][3],pa,b3);
                    pa=pk2(a0.z); fma2(acc[2][0],pa,b0); fma2(acc[2][1],pa,b1); fma2(acc[2][2],pa,b2); fma2(acc[2][3],pa,b3);
                    pa=pk2(a0.w); fma2(acc[3][0],pa,b0); fma2(acc[3][1],pa,b1); fma2(acc[3][2],pa,b2); fma2(acc[3][3],pa,b3);
                    pa=pk2(a1.x); fma2(acc[4][0],pa,b0); fma2(acc[4][1],pa,b1); fma2(acc[4][2],pa,b2); fma2(acc[4][3],pa,b3);
                    pa=pk2(a1.y); fma2(acc[5][0],pa,b0); fma2(acc[5][1],pa,b1); fma2(acc[5][2],pa,b2); fma2(acc[5][3],pa,b3);
                    pa=pk2(a1.z); fma2(acc[6][0],pa,b0); fma2(acc[6][1],pa,b1); fma2(acc[6][2],pa,b2); fma2(acc[6][3],pa,b3);
                    pa=pk2(a1.w); fma2(acc[7][0],pa,b0); fma2(acc[7][1],pa,b1); fma2(acc[7][2],pa,b2); fma2(acc[7][3],pa,b3);
                }
                p ^= 1;
            }
        }

        // fused LSTM cell: 8 rows x hidden pair (2tc, 2tc+1), all in registers
        const int hc = ct*32 + 2*tc;
        #pragma unroll
        for (int r=0;r<8;r++){
            int m = ml[ti*8 + r];
            if (m < 0) continue;
            const float* xg = g_xg + (size_t)m*G4 + hc;
            float2 gi = *(const float2*)(xg);
            float2 gf = *(const float2*)(xg + 512);
            float2 gg = *(const float2*)(xg + 1024);
            float2 go = *(const float2*)(xg + 1536);
            float2 xi = up2(acc[r][0]), xf = up2(acc[r][1]);
            float2 xgg= up2(acc[r][2]), xo = up2(acc[r][3]);
            float2 cp = (s > 0) ? *(const float2*)(g_c + (size_t)(m-1)*RNN + hc)
                                : make_float2(0.f, 0.f);
            float cn0 = sigf(xf.x+gf.x)*cp.x + sigf(xi.x+gi.x)*tanhf(xgg.x+gg.x);
            float cn1 = sigf(xf.y+gf.y)*cp.y + sigf(xi.y+gi.y)*tanhf(xgg.y+gg.y);
            float hn0 = sigf(xo.x+go.x)*tanhf(cn0);
            float hn1 = sigf(xo.y+go.y)*tanhf(cn1);
            *(float2*)(g_h + (size_t)m*RNN + hc) = make_float2(hn0, hn1);
            *(float2*)(g_c + (size_t)m*RNN + hc) = make_float2(cn0, cn1);
        }
    }
}

// ---------------- phase C v2: out = h @ W_out^T + b_out, 128x128 tiles ---------
__global__ void __launch_bounds__(256, 2) k_out(
    const float* __restrict__ Wout, const float* __restrict__ bout,
    float* __restrict__ out)
{
    __shared__ __align__(16) float As[2][16][132];
    __shared__ __align__(16) float Ws[2][16][132];
    __shared__ int msrc[128];
    const int tid = threadIdx.x;
    const int rt = blockIdx.x >> 3, ct = blockIdx.x & 7;
    const int mo0 = rt*128, n0 = ct*128;
    const int ti = tid >> 4, tc = tid & 15;
    const int ar0 = tid & 127, sg0 = tid >> 7;

    if (tid < 128){
        int mo = mo0 + tid;
        if (mo >= MROWS) mo = MROWS - 1;
        int b = mo / 1023;
        msrc[tid] = b*1024 + (mo - b*1023);
    }
    __syncthreads();

    u64 acc[8][4];
    #pragma unroll
    for (int r=0;r<8;r++){
        #pragma unroll
        for (int p=0;p<4;p++) acc[r][p] = 0;
    }

    {
        const float* abase = g_h + (size_t)msrc[ar0]*RNN;
        int nc = n0 + ar0;
        const float* wbase = Wout + (size_t)(nc < NOUT ? nc : 0)*RNN;

        float4 aV[2], wV[2];
        #pragma unroll
        for (int i=0;i<2;i++){
            aV[i] = *(const float4*)(abase + (sg0+2*i)*4);
            wV[i] = *(const float4*)(wbase + (sg0+2*i)*4);
        }
        int p = 0;
        for (int kk = 0; kk < RNN; kk += 16){
            #pragma unroll
            for (int i=0;i<2;i++){
                int seg = sg0 + 2*i;
                As[p][seg*4+0][ar0]=aV[i].x; As[p][seg*4+1][ar0]=aV[i].y;
                As[p][seg*4+2][ar0]=aV[i].z; As[p][seg*4+3][ar0]=aV[i].w;
                Ws[p][seg*4+0][ar0]=wV[i].x; Ws[p][seg*4+1][ar0]=wV[i].y;
                Ws[p][seg*4+2][ar0]=wV[i].z; Ws[p][seg*4+3][ar0]=wV[i].w;
            }
            __syncthreads();
            if (kk + 16 < RNN){
                #pragma unroll
                for (int i=0;i<2;i++){
                    aV[i] = *(const float4*)(abase + kk+16 + (sg0+2*i)*4);
                    wV[i] = *(const float4*)(wbase + kk+16 + (sg0+2*i)*4);
                }
            }
            #pragma unroll
            for (int k=0;k<16;k++){
                float4 a0 = *(const float4*)&As[p][k][ti*8];
                float4 a1 = *(const float4*)&As[p][k][ti*8+4];
                u64 b0 = *(const u64*)&Ws[p][k][2*tc];
                u64 b1 = *(const u64*)&Ws[p][k][2*tc+32];
                u64 b2 = *(const u64*)&Ws[p][k][2*tc+64];
                u64 b3 = *(const u64*)&Ws[p][k][2*tc+96];
                u64 pa;
                pa=pk2(a0.x); fma2(acc[0][0],pa,b0); fma2(acc[0][1],pa,b1); fma2(acc[0][2],pa,b2); fma2(acc[0][3],pa,b3);
                pa=pk2(a0.y); fma2(acc[1][0],pa,b0); fma2(acc[1][1],pa,b1); fma2(acc[1][2],pa,b2); fma2(acc[1][3],pa,b3);
                pa=pk2(a0.z); fma2(acc[2][0],pa,b0); fma2(acc[2][1],pa,b1); fma2(acc[2][2],pa,b2); fma2(acc[2][3],pa,b3);
                pa=pk2(a0.w); fma2(acc[3][0],pa,b0); fma2(acc[3][1],pa,b1); fma2(acc[3][2],pa,b2); fma2(acc[3][3],pa,b3);
                pa=pk2(a1.x); fma2(acc[4][0],pa,b0); fma2(acc[4][1],pa,b1); fma2(acc[4][2],pa,b2); fma2(acc[4][3],pa,b3);
                pa=pk2(a1.y); fma2(acc[5][0],pa,b0); fma2(acc[5][1],pa,b1); fma2(acc[5][2],pa,b2); fma2(acc[5][3],pa,b3);
                pa=pk2(a1.z); fma2(acc[6][0],pa,b0); fma2(acc[6][1],pa,b1); fma2(acc[6][2],pa,b2); fma2(acc[6][3],pa,b3);
                pa=pk2(a1.w); fma2(acc[7][0],pa,b0); fma2(acc[7][1],pa,b1); fma2(acc[7][2],pa,b2); fma2(acc[7][3],pa,b3);
            }
            p ^= 1;
        }
    }

    #pragma unroll
    for (int r=0;r<8;r++){
        int mo = mo0 + ti*8 + r;
        if (mo >= MROWS) continue;
        #pragma unroll
        for (int p=0;p<4;p++){
            float2 v = up2(acc[r][p]);
            int n = n0 + 2*tc + 32*p;
            #pragma unroll
            for (int j=0;j<2;j++){
                int nn = n + j;
                if (nn < NOUT){
                    float val = (j ? v.y : v.x) + bout[nn];
                    size_t dst;
                    if (nn < 320)       dst = (size_t)mo*320 + nn;
                    else if (nn < 640)  dst = S1   + (size_t)mo*320 + (nn-320);
                    else if (nn < 960)  dst = 2*S1 + (size_t)mo*320 + (nn-640);
                    else                dst = 3*S1 + (size_t)mo;
                    out[dst] = val;
                }
            }
        }
    }
}

// ---------------- in-place log-softmax over mixture groups of 5 ----------------
__global__ void k_lsm(float* __restrict__ out){
    size_t g = (size_t)blockIdx.x*256 + threadIdx.x;
    if (g >= (size_t)MROWS*64) return;
    float* p = out + g*5;
    float a0=p[0], a1=p[1], a2=p[2], a3=p[3], a4=p[4];
    float mx = fmaxf(fmaxf(fmaxf(a0,a1), fmaxf(a2,a3)), a4);
    float sum = expf(a0-mx)+expf(a1-mx)+expf(a2-mx)+expf(a3-mx)+expf(a4-mx);
    float l = mx + logf(sum);
    p[0]=a0-l; p[1]=a1-l; p[2]=a2-l; p[3]=a3-l; p[4]=a4-l;
}

// ---------------- launch ----------------
extern "C" void kernel_launch(void* const* d_in, const int* in_sizes, int n_in,
                              void* d_out, int out_size) {
    const float* z    = (const float*)d_in[0];
    const int*   act  = (const int*)  d_in[1];
    const int*   don  = (const int*)  d_in[2];
    const float* emb  = (const float*)d_in[3];
    const float* Wih  = (const float*)d_in[4];
    const float* Whh  = (const float*)d_in[5];
    const float* bih  = (const float*)d_in[6];
    const float* bhh  = (const float*)d_in[7];
    const float* Wout = (const float*)d_in[8];
    const float* bout = (const float*)d_in[9];
    float* out = (float*)d_out;

    k_zero<<<1, 64>>>();
    k_seg<<<NINST/256, 256>>>(don);
    k_phaseA<<<(NINST/64)*(G4/64), 256>>>(z, act, emb, Wih, bih, bhh);
    for (int s = 0; s < SMAX; ++s){
        int g = (s == 0) ? 2048 : ((NINST >> s) / 8);
        if (g < 64)   g = 64;
        if (g > 2048) g = 2048;
        k_rec<<<g, 256>>>(Whh, s);
    }
    k_out<<<512*8, 256>>>(Wout, bout, out);
    k_lsm<<<(int)(((size_t)MROWS*64 + 255)/256), 256>>>(out);
}